// round 1
// baseline (speedup 1.0000x reference)
#include <cuda_runtime.h>
#include <math.h>

#define NN 50000     // nodes
#define NE 1600000   // edges
#define AD 92        // atom dim
#define ED 41        // edge dim
#define ZD 225       // 2*AD + ED
#define NL 4
#define HID 128
#define NG 256
#define PD 184       // 2*AD (f-part | s-part)

#define GRID 1184

// ---------------- device scratch (static globals; no allocation) ----------------
__device__ __align__(16) float g_H[NN * AD];      // node features (updated per layer)
__device__ __align__(16) float g_Pd[NN * PD];     // dst-side node partials: [f(92) | s(92)] (+biases folded)
__device__ __align__(16) float g_Ps[NN * PD];     // src-side node partials
__device__ float g_agg[NN * AD];                  // message aggregation
__device__ float g_stats[2 * AD];                 // per-channel sum, sumsq
__device__ float g_pool[2 * NG];                  // graph sums, counts
__device__ int   g_flags[2];                      // [0]: edge_index is int64, [1]: batch is int64

// ---------------- helpers ----------------
__device__ __forceinline__ float sigmoidf_(float x) {
    return __fdividef(1.f, 1.f + __expf(-x));
}
__device__ __forceinline__ float softplusf_(float x) {
    // stable: max(x,0) + log(1 + exp(-|x|)); arg of log in (1,2] so fast log is accurate enough
    return fmaxf(x, 0.f) + __logf(1.f + __expf(-fabsf(x)));
}

// ---------------- dtype detection (int32 vs int64 inputs) ----------------
__global__ void detect_kernel(const void* eidx, const void* batch) {
    if (threadIdx.x == 0 && blockIdx.x == 0) {
        // edge_index: random values in [0,50000). If int64, every odd 32-bit word is 0.
        const int* p = (const int*)eidx;
        int a = 1;
        for (int i = 0; i < 64; i++) { if (p[2 * i + 1] != 0) { a = 0; break; } }
        g_flags[0] = a;
        // batch: sorted values; mid-array values ~128 (nonzero). Probe odd words near word 25000.
        const int* q = (const int*)batch;
        int b = 1;
        for (int i = 25001; i < 25128; i += 2) { if (q[i] != 0) { b = 0; break; } }
        g_flags[1] = b;
    }
}

// ---------------- copy x -> H ----------------
__global__ void copy_kernel(float* __restrict__ dst, const float* __restrict__ src, int n) {
    for (int i = blockIdx.x * blockDim.x + threadIdx.x; i < n; i += gridDim.x * blockDim.x)
        dst[i] = src[i];
}

// ---------------- node partial GEMM: out[row][0:92] = A@Wf (+bf), out[row][92:184] = A@Ws (+bs) -----
// K = 92. 32 rows/tile. 184 threads: thread = (eg = t/23 -> 4 rows) x (cg = t%23 -> 4 cols).
__global__ __launch_bounds__(184) void prep_kernel(
    const float* __restrict__ A,
    const float* __restrict__ Wfp, const float* __restrict__ Wsp,   // [92][92] slices (row-major, ld=AD)
    const float* __restrict__ bfp, const float* __restrict__ bsp,   // may be null
    float* __restrict__ out)
{
    extern __shared__ float sm[];
    float* Wsm = sm;              // [92][184]
    float* Asm = sm + AD * PD;    // [92][32] (transposed tile)
    const int t = threadIdx.x;
    for (int i = t; i < AD * AD; i += 184) {
        int k = i / AD, j = i - k * AD;
        Wsm[k * PD + j]      = Wfp[i];
        Wsm[k * PD + AD + j] = Wsp[i];
    }
    const int cg = t % 23, eg = t / 23;
    const int j0 = 4 * cg;
    const int ntiles = (NN + 31) / 32;
    for (int tile = blockIdx.x; tile < ntiles; tile += gridDim.x) {
        const int base = tile * 32;
        __syncthreads();
        for (int i = t; i < 32 * AD; i += 184) {
            int r = i / AD, k = i - r * AD;
            int row = base + r;
            Asm[k * 32 + r] = (row < NN) ? A[(size_t)row * AD + k] : 0.f;
        }
        __syncthreads();
        float accf[4][4] = {}, accs[4][4] = {};
        #pragma unroll 4
        for (int k = 0; k < AD; k++) {
            const float4 av = *(const float4*)(Asm + k * 32 + 4 * eg);
            const float4 wf = *(const float4*)(Wsm + k * PD + j0);
            const float4 ws = *(const float4*)(Wsm + k * PD + AD + j0);
            const float a4[4] = {av.x, av.y, av.z, av.w};
            const float f4[4] = {wf.x, wf.y, wf.z, wf.w};
            const float s4[4] = {ws.x, ws.y, ws.z, ws.w};
            #pragma unroll
            for (int r = 0; r < 4; r++)
                #pragma unroll
                for (int c = 0; c < 4; c++) {
                    accf[r][c] += a4[r] * f4[c];
                    accs[r][c] += a4[r] * s4[c];
                }
        }
        float bf4[4] = {0.f, 0.f, 0.f, 0.f}, bs4[4] = {0.f, 0.f, 0.f, 0.f};
        if (bfp) {
            #pragma unroll
            for (int c = 0; c < 4; c++) { bf4[c] = bfp[j0 + c]; bs4[c] = bsp[j0 + c]; }
        }
        #pragma unroll
        for (int r = 0; r < 4; r++) {
            const int row = base + 4 * eg + r;
            if (row < NN) {
                float4 of, os;
                of.x = accf[r][0] + bf4[0]; of.y = accf[r][1] + bf4[1];
                of.z = accf[r][2] + bf4[2]; of.w = accf[r][3] + bf4[3];
                os.x = accs[r][0] + bs4[0]; os.y = accs[r][1] + bs4[1];
                os.z = accs[r][2] + bs4[2]; os.w = accs[r][3] + bs4[3];
                *(float4*)(out + (size_t)row * PD + j0)      = of;
                *(float4*)(out + (size_t)row * PD + AD + j0) = os;
            }
        }
    }
}

// ---------------- edge kernel: per-edge gate*softplus message + scatter-add ----------------
// 32 edges/tile, K=41 edge-GEMM fused; gathers node partials; atomics into agg.
__global__ __launch_bounds__(184) void edge_kernel(
    const float* __restrict__ eattr, const void* __restrict__ eidx,
    const float* __restrict__ Wfe, const float* __restrict__ Wse,   // [41][92] slices
    const float* __restrict__ Pd, const float* __restrict__ Ps,
    float* __restrict__ agg)
{
    __shared__ __align__(16) float Wsm[ED * PD];   // [41][184]
    __shared__ __align__(16) float Esm[ED * 32];   // [41][32] transposed edge_attr tile
    __shared__ int dsm[32], ssm[32];
    const int t = threadIdx.x;
    for (int i = t; i < ED * AD; i += 184) {
        int k = i / AD, j = i - k * AD;
        Wsm[k * PD + j]      = Wfe[i];
        Wsm[k * PD + AD + j] = Wse[i];
    }
    const int ll = g_flags[0];
    const int cg = t % 23, eg = t / 23;
    const int j0 = 4 * cg;
    const int ntiles = NE / 32;
    for (int tile = blockIdx.x; tile < ntiles; tile += gridDim.x) {
        const int ebase = tile * 32;
        __syncthreads();
        if (t < 32) {
            const int e = ebase + t;
            if (ll) {
                ssm[t] = (int)((const long long*)eidx)[e];
                dsm[t] = (int)((const long long*)eidx)[NE + e];
            } else {
                ssm[t] = ((const int*)eidx)[e];
                dsm[t] = ((const int*)eidx)[NE + e];
            }
        }
        for (int i = t; i < 32 * ED; i += 184) {
            int e = i / ED, k = i - e * ED;
            Esm[k * 32 + e] = eattr[(size_t)(ebase + e) * ED + k];
        }
        __syncthreads();
        float accf[4][4] = {}, accs[4][4] = {};
        #pragma unroll
        for (int k = 0; k < ED; k++) {
            const float4 ev = *(const float4*)(Esm + k * 32 + 4 * eg);
            const float4 wf = *(const float4*)(Wsm + k * PD + j0);
            const float4 ws = *(const float4*)(Wsm + k * PD + AD + j0);
            const float e4[4] = {ev.x, ev.y, ev.z, ev.w};
            const float f4[4] = {wf.x, wf.y, wf.z, wf.w};
            const float s4[4] = {ws.x, ws.y, ws.z, ws.w};
            #pragma unroll
            for (int r = 0; r < 4; r++)
                #pragma unroll
                for (int c = 0; c < 4; c++) {
                    accf[r][c] += e4[r] * f4[c];
                    accs[r][c] += e4[r] * s4[c];
                }
        }
        #pragma unroll
        for (int r = 0; r < 4; r++) {
            const int ee = 4 * eg + r;
            const int d = dsm[ee], s = ssm[ee];
            const float4 pdf = *(const float4*)(Pd + (size_t)d * PD + j0);
            const float4 pds = *(const float4*)(Pd + (size_t)d * PD + AD + j0);
            const float4 psf = *(const float4*)(Ps + (size_t)s * PD + j0);
            const float4 pss = *(const float4*)(Ps + (size_t)s * PD + AD + j0);
            float fv[4], sv[4];
            fv[0] = accf[r][0] + pdf.x + psf.x;  sv[0] = accs[r][0] + pds.x + pss.x;
            fv[1] = accf[r][1] + pdf.y + psf.y;  sv[1] = accs[r][1] + pds.y + pss.y;
            fv[2] = accf[r][2] + pdf.z + psf.z;  sv[2] = accs[r][2] + pds.z + pss.z;
            fv[3] = accf[r][3] + pdf.w + psf.w;  sv[3] = accs[r][3] + pds.w + pss.w;
            float* ap = agg + (size_t)d * AD + j0;
            #pragma unroll
            for (int c = 0; c < 4; c++) {
                const float m = sigmoidf_(fv[c]) * softplusf_(sv[c]);
                atomicAdd(ap + c, m);
            }
        }
    }
}

// ---------------- batchnorm stats ----------------
__global__ void bn_stats(const float* __restrict__ agg, float* __restrict__ stats) {
    const int c = threadIdx.x;  // blockDim = 92
    float s = 0.f, q = 0.f;
    for (int i = blockIdx.x; i < NN; i += gridDim.x) {
        const float v = agg[(size_t)i * AD + c];
        s += v; q += v * v;
    }
    atomicAdd(&stats[c], s);
    atomicAdd(&stats[AD + c], q);
}

// ---------------- batchnorm apply + residual + leaky (in place on H) ----------------
__global__ void bn_apply(const float* __restrict__ agg, float* __restrict__ H,
                         const float* __restrict__ stats,
                         const float* __restrict__ gamma, const float* __restrict__ beta)
{
    const float invN = 1.f / (float)NN;
    for (int idx = blockIdx.x * blockDim.x + threadIdx.x; idx < NN * AD;
         idx += gridDim.x * blockDim.x) {
        const int c = idx % AD;
        const float mean = stats[c] * invN;
        const float var  = stats[AD + c] * invN - mean * mean;
        const float inv  = rsqrtf(var + 1e-5f);
        float v = (agg[idx] - mean) * inv * gamma[c] + beta[c] + H[idx];
        H[idx] = v > 0.f ? v : 0.01f * v;
    }
}

// ---------------- final MLP (92->128->1) + per-graph sum/count pooling ----------------
__global__ __launch_bounds__(128) void mlp_pool(
    const float* __restrict__ H,
    const float* __restrict__ W1, const float* __restrict__ b1,
    const float* __restrict__ W2, const float* __restrict__ b2,
    const void* __restrict__ batch, float* __restrict__ pool)
{
    extern __shared__ float sm[];
    float* Wsm = sm;                 // [92][128]
    float* hsT = sm + AD * HID;      // [92][8]
    float* red = hsT + AD * 8;       // [4][8]
    const int t = threadIdx.x;
    for (int i = t; i < AD * HID; i += 128) Wsm[i] = W1[i];
    const float b1t = b1[t];
    const float w2t = W2[t];
    const int lane = t & 31, wid = t >> 5;
    const int ll = g_flags[1];
    const int ntiles = (NN + 7) / 8;
    for (int tile = blockIdx.x; tile < ntiles; tile += gridDim.x) {
        const int base = tile * 8;
        __syncthreads();
        for (int i = t; i < 8 * AD; i += 128) {
            int n = i / AD, k = i - n * AD;
            int node = base + n;
            hsT[k * 8 + n] = (node < NN) ? H[(size_t)node * AD + k] : 0.f;
        }
        __syncthreads();
        float acc[8] = {};
        #pragma unroll 4
        for (int k = 0; k < AD; k++) {
            const float w = Wsm[k * HID + t];
            const float4 h0 = *(const float4*)(hsT + k * 8);
            const float4 h1 = *(const float4*)(hsT + k * 8 + 4);
            acc[0] += h0.x * w; acc[1] += h0.y * w; acc[2] += h0.z * w; acc[3] += h0.w * w;
            acc[4] += h1.x * w; acc[5] += h1.y * w; acc[6] += h1.z * w; acc[7] += h1.w * w;
        }
        #pragma unroll
        for (int n = 0; n < 8; n++) {
            float v = acc[n] + b1t;
            v = v > 0.f ? v : 0.01f * v;
            v *= w2t;
            #pragma unroll
            for (int o = 16; o > 0; o >>= 1) v += __shfl_down_sync(0xffffffffu, v, o);
            if (lane == 0) red[wid * 8 + n] = v;
        }
        __syncthreads();
        if (t < 8) {
            const int node = base + t;
            if (node < NN) {
                const float s2 = red[t] + red[8 + t] + red[16 + t] + red[24 + t] + b2[0];
                const int g = ll ? (int)((const long long*)batch)[node]
                                 : ((const int*)batch)[node];
                atomicAdd(&pool[g], s2);
                atomicAdd(&pool[NG + g], 1.f);
            }
        }
    }
}

__global__ void finalize_kernel(const float* __restrict__ pool, float* __restrict__ out) {
    const int g = threadIdx.x;
    if (g < NG) out[g] = pool[g] / fmaxf(pool[NG + g], 1.f);
}

// ---------------- host orchestration ----------------
extern "C" void kernel_launch(void* const* d_in, const int* in_sizes, int n_in,
                              void* d_out, int out_size)
{
    const float* x     = (const float*)d_in[0];
    const void*  eidx  = d_in[1];
    const float* eattr = (const float*)d_in[2];
    const void*  batch = d_in[3];
    const float* Wf    = (const float*)d_in[4];
    const float* bf    = (const float*)d_in[5];
    const float* Ws    = (const float*)d_in[6];
    const float* bs    = (const float*)d_in[7];
    const float* gamma = (const float*)d_in[8];
    const float* beta  = (const float*)d_in[9];
    const float* W1    = (const float*)d_in[10];
    const float* b1    = (const float*)d_in[11];
    const float* W2    = (const float*)d_in[12];
    const float* b2    = (const float*)d_in[13];
    float* out = (float*)d_out;

    const int PREP_SMEM = (AD * PD + AD * 32) * 4;        // 79488 B
    const int MLP_SMEM  = (AD * HID + AD * 8 + 32) * 4;   // 50304 B
    cudaFuncSetAttribute(prep_kernel, cudaFuncAttributeMaxDynamicSharedMemorySize, PREP_SMEM);
    cudaFuncSetAttribute(mlp_pool,    cudaFuncAttributeMaxDynamicSharedMemorySize, MLP_SMEM);

    void *pH, *pPd, *pPs, *pagg, *pstats, *ppool;
    cudaGetSymbolAddress(&pH, g_H);
    cudaGetSymbolAddress(&pPd, g_Pd);
    cudaGetSymbolAddress(&pPs, g_Ps);
    cudaGetSymbolAddress(&pagg, g_agg);
    cudaGetSymbolAddress(&pstats, g_stats);
    cudaGetSymbolAddress(&ppool, g_pool);

    detect_kernel<<<1, 32>>>(eidx, batch);
    copy_kernel<<<GRID, 256>>>((float*)pH, x, NN * AD);

    for (int l = 0; l < NL; l++) {
        const float* Wfl = Wf + (size_t)l * ZD * AD;
        const float* Wsl = Ws + (size_t)l * ZD * AD;
        prep_kernel<<<GRID, 184, PREP_SMEM>>>((const float*)pH, Wfl, Wsl,
                                              bf + l * AD, bs + l * AD, (float*)pPd);
        prep_kernel<<<GRID, 184, PREP_SMEM>>>((const float*)pH, Wfl + 92 * AD, Wsl + 92 * AD,
                                              nullptr, nullptr, (float*)pPs);
        cudaMemsetAsync(pagg, 0, (size_t)NN * AD * sizeof(float));
        edge_kernel<<<GRID, 184>>>(eattr, eidx, Wfl + 184 * AD, Wsl + 184 * AD,
                                   (const float*)pPd, (const float*)pPs, (float*)pagg);
        cudaMemsetAsync(pstats, 0, 2 * AD * sizeof(float));
        bn_stats<<<256, 92>>>((const float*)pagg, (float*)pstats);
        bn_apply<<<GRID, 256>>>((const float*)pagg, (float*)pH, (const float*)pstats,
                                gamma + l * AD, beta + l * AD);
    }

    cudaMemsetAsync(ppool, 0, 2 * NG * sizeof(float));
    mlp_pool<<<GRID, 128, MLP_SMEM>>>((const float*)pH, W1, b1, W2, b2, batch, (float*)ppool);
    finalize_kernel<<<1, NG>>>((const float*)ppool, out);
}

// round 3
// speedup vs baseline: 1.2069x; 1.2069x over previous
#include <cuda_runtime.h>
#include <math.h>

#define NN 50000     // nodes
#define NE 1600000   // edges
#define AD 92        // atom dim
#define ED 41        // edge dim
#define ZD 225       // 2*AD + ED
#define NL 4
#define HID 128
#define NG 256
#define PD 184       // 2*AD (f-part | s-part)
#define ET 64        // edges per tile
#define EGRID 888
#define GRID 1184

typedef unsigned long long u64;

// ---------------- device scratch ----------------
__device__ __align__(16) float g_H[NN * AD];
__device__ __align__(16) float g_Pd[NN * PD];
__device__ __align__(16) float g_Ps[NN * PD];
__device__ __align__(16) float g_agg[NN * AD];
__device__ float g_stats[2 * AD];
__device__ float g_pool[2 * NG];
__device__ int   g_flags[2];

// ---------------- f32x2 packed helpers (Blackwell) ----------------
__device__ __forceinline__ u64 fma2(u64 a, u64 b, u64 c) {
    u64 d; asm("fma.rn.f32x2 %0, %1, %2, %3;" : "=l"(d) : "l"(a), "l"(b), "l"(c)); return d;
}
__device__ __forceinline__ u64 add2(u64 a, u64 b) {
    u64 d; asm("add.rn.f32x2 %0, %1, %2;" : "=l"(d) : "l"(a), "l"(b)); return d;
}
__device__ __forceinline__ u64 pack2(float x, float y) {
    u64 d; asm("mov.b64 %0, {%1, %2};" : "=l"(d) : "f"(x), "f"(y)); return d;
}
__device__ __forceinline__ void unpack2(u64 v, float& x, float& y) {
    asm("mov.b64 {%0, %1}, %2;" : "=f"(x), "=f"(y) : "l"(v));
}
__device__ __forceinline__ void red_add_v4(float* p, float a, float b, float c, float d) {
    asm volatile("red.global.add.v4.f32 [%0], {%1, %2, %3, %4};"
                 :: "l"(p), "f"(a), "f"(b), "f"(c), "f"(d) : "memory");
}
__device__ __forceinline__ float sigmoidf_(float x) {
    return __fdividef(1.f, 1.f + __expf(-x));
}
__device__ __forceinline__ float softplusf_(float x) {
    return fmaxf(x, 0.f) + __logf(1.f + __expf(-fabsf(x)));
}

// ---------------- dtype detection ----------------
__global__ void detect_kernel(const void* eidx, const void* batch) {
    if (threadIdx.x == 0 && blockIdx.x == 0) {
        const int* p = (const int*)eidx;
        int a = 1;
        for (int i = 0; i < 64; i++) { if (p[2 * i + 1] != 0) { a = 0; break; } }
        g_flags[0] = a;
        const int* q = (const int*)batch;
        int b = 1;
        for (int i = 25001; i < 25128; i += 2) { if (q[i] != 0) { b = 0; break; } }
        g_flags[1] = b;
    }
}

// ---------------- copy x -> H (vectorized) ----------------
__global__ void copy_kernel(float4* __restrict__ dst, const float4* __restrict__ src, int n4) {
    for (int i = blockIdx.x * blockDim.x + threadIdx.x; i < n4; i += gridDim.x * blockDim.x)
        dst[i] = src[i];
}

// ---------------- fused node partials: Pd[f|s] and Ps[f|s] in one pass -------------
// W in smem: [92][368] = [Wf_dst | Ws_dst | Wf_src | Ws_src]. 368 threads.
// Each thread: 8 rows (8*eg..) x 4 cols (4*cg..), packed f32x2 accumulators.
__global__ __launch_bounds__(368, 1) void prep_kernel(
    const float* __restrict__ H,
    const float* __restrict__ Wfl, const float* __restrict__ Wsl,   // full layer [225][92]
    const float* __restrict__ bfp, const float* __restrict__ bsp,
    float* __restrict__ Pd, float* __restrict__ Ps)
{
    extern __shared__ float sm[];
    float* Wsm = sm;             // [92][368]
    float* Asm = sm + AD * 368;  // [92][32] transposed
    const int t = threadIdx.x;
    {   // W fill: fixed column j=t, loop k. Conflict-free stores, coalesced loads.
        const float* src; int off;
        if (t < 92)       { src = Wfl;            off = t; }
        else if (t < 184) { src = Wsl;            off = t - 92; }
        else if (t < 276) { src = Wfl + 92 * AD;  off = t - 184; }
        else              { src = Wsl + 92 * AD;  off = t - 276; }
        for (int k = 0; k < AD; k++)
            Wsm[k * 368 + t] = src[k * AD + off];
    }
    const int cg = t % 92, eg = t / 92;
    const int j0 = 4 * cg;
    float4 bias = {0.f, 0.f, 0.f, 0.f};
    if (cg < 23)       bias = *(const float4*)(bfp + j0);
    else if (cg < 46)  bias = *(const float4*)(bsp + j0 - 92);
    float* outbase = (j0 < 184) ? Pd : Ps;
    const int ocol = (j0 < 184) ? j0 : (j0 - 184);
    const int ntiles = (NN + 31) / 32;
    for (int tile = blockIdx.x; tile < ntiles; tile += gridDim.x) {
        const int base = tile * 32;
        __syncthreads();
        if (t < 256) {  // A fill: lane-major rows -> conflict-free stores
            const int r = t & 31, part = t >> 5;
            const int row = base + r;
            const float* src = H + (size_t)row * AD;
            for (int k = part; k < AD; k += 8)
                Asm[k * 32 + r] = (row < NN) ? src[k] : 0.f;
        }
        __syncthreads();
        u64 acc[8][2] = {};
        for (int k = 0; k < AD; k++) {
            const ulonglong2 w = *(const ulonglong2*)(Wsm + k * 368 + j0);
            const float4 a0 = *(const float4*)(Asm + k * 32 + 8 * eg);
            const float4 a1 = *(const float4*)(Asm + k * 32 + 8 * eg + 4);
            const float av[8] = {a0.x, a0.y, a0.z, a0.w, a1.x, a1.y, a1.z, a1.w};
            #pragma unroll
            for (int r = 0; r < 8; r++) {
                const u64 ap = pack2(av[r], av[r]);
                acc[r][0] = fma2(ap, w.x, acc[r][0]);
                acc[r][1] = fma2(ap, w.y, acc[r][1]);
            }
        }
        #pragma unroll
        for (int r = 0; r < 8; r++) {
            const int row = base + 8 * eg + r;
            if (row < NN) {
                float x0, x1, x2, x3;
                unpack2(acc[r][0], x0, x1); unpack2(acc[r][1], x2, x3);
                float4 o;
                o.x = x0 + bias.x; o.y = x1 + bias.y; o.z = x2 + bias.z; o.w = x3 + bias.w;
                *(float4*)(outbase + (size_t)row * PD + ocol) = o;
            }
        }
    }
}

// ---------------- edge kernel: 64 edges/tile, packed f32x2 edge-GEMM + gather + red.v4 ---
__global__ __launch_bounds__(184, 3) void edge_kernel(
    const float* __restrict__ eattr, const void* __restrict__ eidx,
    const float* __restrict__ Wfe, const float* __restrict__ Wse,   // [41][92] slices
    const float* __restrict__ Pd, const float* __restrict__ Ps,
    float* __restrict__ agg)
{
    __shared__ __align__(16) float Wsm[ED * PD];   // [41][184]
    __shared__ __align__(16) float Esm[ED * ET];   // [41][64] transposed
    __shared__ int dsm[ET], ssm[ET];
    const int t = threadIdx.x;
    {   // W fill: fixed column j=t, loop k
        for (int k = 0; k < ED; k++) {
            float v = (t < AD) ? Wfe[k * AD + t] : Wse[k * AD + (t - AD)];
            Wsm[k * PD + t] = v;
        }
    }
    const int ll = g_flags[0];
    const int cg = t % 23, eg = t / 23;
    const int j0 = 4 * cg;
    const int ntiles = NE / ET;
    for (int tile = blockIdx.x; tile < ntiles; tile += gridDim.x) {
        const int ebase = tile * ET;
        __syncthreads();
        if (t < 128) {  // E fill: lane = edge -> conflict-free stores, L1-friendly loads
            const int e = t & 63, h = t >> 6;
            const float* src = eattr + (size_t)(ebase + e) * ED;
            for (int k = h; k < ED; k += 2) Esm[k * ET + e] = src[k];
        } else if (t < 160) {
            const int i = t - 128;
            if (ll) {
                const long long* ip = (const long long*)eidx;
                ssm[2*i]   = (int)ip[ebase + 2*i];      ssm[2*i+1] = (int)ip[ebase + 2*i+1];
                dsm[2*i]   = (int)ip[NE + ebase + 2*i]; dsm[2*i+1] = (int)ip[NE + ebase + 2*i+1];
            } else {
                const int* ip = (const int*)eidx;
                ssm[2*i]   = ip[ebase + 2*i];      ssm[2*i+1] = ip[ebase + 2*i+1];
                dsm[2*i]   = ip[NE + ebase + 2*i]; dsm[2*i+1] = ip[NE + ebase + 2*i+1];
            }
        }
        __syncthreads();
        u64 accf[8][2] = {}, accs[8][2] = {};
        for (int k = 0; k < ED; k++) {
            const ulonglong2 wf = *(const ulonglong2*)(Wsm + k * PD + j0);
            const ulonglong2 ws = *(const ulonglong2*)(Wsm + k * PD + AD + j0);
            const float4 e0 = *(const float4*)(Esm + k * ET + 8 * eg);
            const float4 e1 = *(const float4*)(Esm + k * ET + 8 * eg + 4);
            const float ev[8] = {e0.x, e0.y, e0.z, e0.w, e1.x, e1.y, e1.z, e1.w};
            #pragma unroll
            for (int r = 0; r < 8; r++) {
                const u64 ep = pack2(ev[r], ev[r]);
                accf[r][0] = fma2(ep, wf.x, accf[r][0]);
                accf[r][1] = fma2(ep, wf.y, accf[r][1]);
                accs[r][0] = fma2(ep, ws.x, accs[r][0]);
                accs[r][1] = fma2(ep, ws.y, accs[r][1]);
            }
        }
        #pragma unroll
        for (int r = 0; r < 8; r++) {
            const int el = 8 * eg + r;
            const int d = dsm[el], s = ssm[el];
            const ulonglong2 pdf = *(const ulonglong2*)(Pd + d * PD + j0);
            const ulonglong2 pds = *(const ulonglong2*)(Pd + d * PD + AD + j0);
            const ulonglong2 psf = *(const ulonglong2*)(Ps + s * PD + j0);
            const ulonglong2 pss = *(const ulonglong2*)(Ps + s * PD + AD + j0);
            const u64 f0 = add2(add2(accf[r][0], pdf.x), psf.x);
            const u64 f1 = add2(add2(accf[r][1], pdf.y), psf.y);
            const u64 s0 = add2(add2(accs[r][0], pds.x), pss.x);
            const u64 s1 = add2(add2(accs[r][1], pds.y), pss.y);
            float fa, fb, fc, fd, sa, sb, sc, sd;
            unpack2(f0, fa, fb); unpack2(f1, fc, fd);
            unpack2(s0, sa, sb); unpack2(s1, sc, sd);
            red_add_v4(agg + d * AD + j0,
                       sigmoidf_(fa) * softplusf_(sa), sigmoidf_(fb) * softplusf_(sb),
                       sigmoidf_(fc) * softplusf_(sc), sigmoidf_(fd) * softplusf_(sd));
        }
    }
}

// ---------------- batchnorm stats ----------------
__global__ void bn_stats(const float* __restrict__ agg, float* __restrict__ stats) {
    const int c = threadIdx.x;  // blockDim = 92
    float s = 0.f, q = 0.f;
    for (int i = blockIdx.x; i < NN; i += gridDim.x) {
        const float v = agg[(size_t)i * AD + c];
        s += v; q += v * v;
    }
    atomicAdd(&stats[c], s);
    atomicAdd(&stats[AD + c], q);
}

// ---------------- batchnorm apply + residual + leaky ----------------
__global__ void bn_apply(const float* __restrict__ agg, float* __restrict__ H,
                         const float* __restrict__ stats,
                         const float* __restrict__ gamma, const float* __restrict__ beta)
{
    const float invN = 1.f / (float)NN;
    for (int idx = blockIdx.x * blockDim.x + threadIdx.x; idx < NN * AD;
         idx += gridDim.x * blockDim.x) {
        const int c = idx % AD;
        const float mean = stats[c] * invN;
        const float var  = stats[AD + c] * invN - mean * mean;
        const float inv  = rsqrtf(var + 1e-5f);
        float v = (agg[idx] - mean) * inv * gamma[c] + beta[c] + H[idx];
        H[idx] = v > 0.f ? v : 0.01f * v;
    }
}

// ---------------- final MLP + pooling ----------------
__global__ __launch_bounds__(128) void mlp_pool(
    const float* __restrict__ H,
    const float* __restrict__ W1, const float* __restrict__ b1,
    const float* __restrict__ W2, const float* __restrict__ b2,
    const void* __restrict__ batch, float* __restrict__ pool)
{
    extern __shared__ float sm[];
    float* Wsm = sm;                 // [92][128]
    float* hsT = sm + AD * HID;      // [92][8]
    float* red = hsT + AD * 8;       // [4][8]
    const int t = threadIdx.x;
    for (int i = t; i < AD * HID; i += 128) Wsm[i] = W1[i];
    const float b1t = b1[t];
    const float w2t = W2[t];
    const int lane = t & 31, wid = t >> 5;
    const int ll = g_flags[1];
    const int ntiles = (NN + 7) / 8;
    for (int tile = blockIdx.x; tile < ntiles; tile += gridDim.x) {
        const int base = tile * 8;
        __syncthreads();
        for (int i = t; i < 8 * AD; i += 128) {
            int n = i / AD, k = i - n * AD;
            int node = base + n;
            hsT[k * 8 + n] = (node < NN) ? H[(size_t)node * AD + k] : 0.f;
        }
        __syncthreads();
        float acc[8] = {};
        #pragma unroll 4
        for (int k = 0; k < AD; k++) {
            const float w = Wsm[k * HID + t];
            const float4 h0 = *(const float4*)(hsT + k * 8);
            const float4 h1 = *(const float4*)(hsT + k * 8 + 4);
            acc[0] += h0.x * w; acc[1] += h0.y * w; acc[2] += h0.z * w; acc[3] += h0.w * w;
            acc[4] += h1.x * w; acc[5] += h1.y * w; acc[6] += h1.z * w; acc[7] += h1.w * w;
        }
        #pragma unroll
        for (int n = 0; n < 8; n++) {
            float v = acc[n] + b1t;
            v = v > 0.f ? v : 0.01f * v;
            v *= w2t;
            #pragma unroll
            for (int o = 16; o > 0; o >>= 1) v += __shfl_down_sync(0xffffffffu, v, o);
            if (lane == 0) red[wid * 8 + n] = v;
        }
        __syncthreads();
        if (t < 8) {
            const int node = base + t;
            if (node < NN) {
                const float s2 = red[t] + red[8 + t] + red[16 + t] + red[24 + t] + b2[0];
                const int g = ll ? (int)((const long long*)batch)[node]
                                 : ((const int*)batch)[node];
                atomicAdd(&pool[g], s2);
                atomicAdd(&pool[NG + g], 1.f);
            }
        }
    }
}

__global__ void finalize_kernel(const float* __restrict__ pool, float* __restrict__ out) {
    const int g = threadIdx.x;
    if (g < NG) out[g] = pool[g] / fmaxf(pool[NG + g], 1.f);
}

// ---------------- host orchestration ----------------
extern "C" void kernel_launch(void* const* d_in, const int* in_sizes, int n_in,
                              void* d_out, int out_size)
{
    const float* x     = (const float*)d_in[0];
    const void*  eidx  = d_in[1];
    const float* eattr = (const float*)d_in[2];
    const void*  batch = d_in[3];
    const float* Wf    = (const float*)d_in[4];
    const float* bf    = (const float*)d_in[5];
    const float* Ws    = (const float*)d_in[6];
    const float* bs    = (const float*)d_in[7];
    const float* gamma = (const float*)d_in[8];
    const float* beta  = (const float*)d_in[9];
    const float* W1    = (const float*)d_in[10];
    const float* b1    = (const float*)d_in[11];
    const float* W2    = (const float*)d_in[12];
    const float* b2    = (const float*)d_in[13];
    float* out = (float*)d_out;

    const int PREP_SMEM = (AD * 368 + AD * 32) * 4;       // 147200 B
    const int MLP_SMEM  = (AD * HID + AD * 8 + 32) * 4;   // 50304 B
    cudaFuncSetAttribute(prep_kernel, cudaFuncAttributeMaxDynamicSharedMemorySize, PREP_SMEM);
    cudaFuncSetAttribute(mlp_pool,    cudaFuncAttributeMaxDynamicSharedMemorySize, MLP_SMEM);

    void *pH, *pPd, *pPs, *pagg, *pstats, *ppool;
    cudaGetSymbolAddress(&pH, g_H);
    cudaGetSymbolAddress(&pPd, g_Pd);
    cudaGetSymbolAddress(&pPs, g_Ps);
    cudaGetSymbolAddress(&pagg, g_agg);
    cudaGetSymbolAddress(&pstats, g_stats);
    cudaGetSymbolAddress(&ppool, g_pool);

    detect_kernel<<<1, 32>>>(eidx, batch);
    copy_kernel<<<GRID, 256>>>((float4*)pH, (const float4*)x, NN * AD / 4);

    for (int l = 0; l < NL; l++) {
        const float* Wfl = Wf + (size_t)l * ZD * AD;
        const float* Wsl = Ws + (size_t)l * ZD * AD;
        prep_kernel<<<148, 368, PREP_SMEM>>>((const float*)pH, Wfl, Wsl,
                                             bf + l * AD, bs + l * AD,
                                             (float*)pPd, (float*)pPs);
        cudaMemsetAsync(pagg, 0, (size_t)NN * AD * sizeof(float));
        edge_kernel<<<EGRID, 184>>>(eattr, eidx, Wfl + 184 * AD, Wsl + 184 * AD,
                                    (const float*)pPd, (const float*)pPs, (float*)pagg);
        cudaMemsetAsync(pstats, 0, 2 * AD * sizeof(float));
        bn_stats<<<256, 92>>>((const float*)pagg, (float*)pstats);
        bn_apply<<<GRID, 256>>>((const float*)pagg, (float*)pH, (const float*)pstats,
                                gamma + l * AD, beta + l * AD);
    }

    cudaMemsetAsync(ppool, 0, 2 * NG * sizeof(float));
    mlp_pool<<<GRID, 128, MLP_SMEM>>>((const float*)pH, W1, b1, W2, b2, batch, (float*)ppool);
    finalize_kernel<<<1, NG>>>((const float*)ppool, out);
}

// round 6
// speedup vs baseline: 1.5552x; 1.2886x over previous
#include <cuda_runtime.h>
#include <cuda_bf16.h>
#include <math.h>
#include <stdint.h>

#define NN 50000     // nodes
#define NE 1600000   // edges
#define AD 92        // atom dim
#define ED 41        // edge dim
#define ZD 225       // 2*AD + ED
#define NL 4
#define HID 128
#define NG 256
#define PD 184       // 2*AD (f-part | s-part)
#define GRID 1184
#define EGRID 444    // persistent CTAs for edge kernel (148*3)

typedef unsigned long long u64;

// ---------------- device scratch ----------------
__device__ __align__(16) float g_H[NN * AD];
__device__ __align__(16) float g_Pd[NN * PD];
__device__ __align__(16) float g_Ps[NN * PD];
__device__ __align__(16) float g_agg[NN * AD];
__device__ float g_stats[2 * AD];
__device__ float g_pool[2 * NG];
__device__ int   g_flags[2];

// ---------------- helpers ----------------
__device__ __forceinline__ u64 fma2(u64 a, u64 b, u64 c) {
    u64 d; asm("fma.rn.f32x2 %0, %1, %2, %3;" : "=l"(d) : "l"(a), "l"(b), "l"(c)); return d;
}
__device__ __forceinline__ u64 pack2(float x, float y) {
    u64 d; asm("mov.b64 %0, {%1, %2};" : "=l"(d) : "f"(x), "f"(y)); return d;
}
__device__ __forceinline__ void unpack2(u64 v, float& x, float& y) {
    asm("mov.b64 {%0, %1}, %2;" : "=f"(x), "=f"(y) : "l"(v));
}
__device__ __forceinline__ void red_add_v2(float* p, float a, float b) {
    asm volatile("red.global.add.v2.f32 [%0], {%1, %2};"
                 :: "l"(p), "f"(a), "f"(b) : "memory");
}
__device__ __forceinline__ float sigmoidf_(float x) {
    return __fdividef(1.f, 1.f + __expf(-x));
}
__device__ __forceinline__ float softplusf_(float x) {
    return fmaxf(x, 0.f) + __logf(1.f + __expf(-fabsf(x)));
}
__device__ __forceinline__ uint32_t smem_u32(const void* p) {
    uint32_t a;
    asm("{ .reg .u64 tmp; cvta.to.shared.u64 tmp, %1; cvt.u32.u64 %0, tmp; }"
        : "=r"(a) : "l"(p));
    return a;
}
__device__ __forceinline__ uint32_t pack_bf16x2(__nv_bfloat16 lo, __nv_bfloat16 hi) {
    return (uint32_t)__bfloat16_as_ushort(lo) | ((uint32_t)__bfloat16_as_ushort(hi) << 16);
}
// split x into bf16 hi + bf16 lo (residual)
__device__ __forceinline__ void bsplit(float x, __nv_bfloat16& h, __nv_bfloat16& l) {
    h = __float2bfloat16_rn(x);
    l = __float2bfloat16_rn(x - __bfloat162float(h));
}
__device__ __forceinline__ void ldmatrix_x4(uint32_t* r, uint32_t addr) {
    asm volatile("ldmatrix.sync.aligned.m8n8.x4.shared.b16 {%0,%1,%2,%3}, [%4];"
                 : "=r"(r[0]), "=r"(r[1]), "=r"(r[2]), "=r"(r[3]) : "r"(addr));
}
__device__ __forceinline__ void mma_bf16(float* c, const uint32_t* a, uint32_t b0, uint32_t b1) {
    asm volatile("mma.sync.aligned.m16n8k16.row.col.f32.bf16.bf16.f32 "
                 "{%0,%1,%2,%3}, {%4,%5,%6,%7}, {%8,%9}, {%0,%1,%2,%3};"
                 : "+f"(c[0]), "+f"(c[1]), "+f"(c[2]), "+f"(c[3])
                 : "r"(a[0]), "r"(a[1]), "r"(a[2]), "r"(a[3]), "r"(b0), "r"(b1));
}

// edge kernel smem: W^T hi + lo, 192 rows x 128B each (K padded to 64 bf16), XOR-swizzled
#define BROWS 192
#define BROWB 128
#define OFF_BH 0
#define OFF_BL (BROWS * BROWB)           // 24576
#define EDGE_SMEM (2 * BROWS * BROWB)    // 49152

// ---------------- dtype detection ----------------
__global__ void detect_kernel(const void* eidx, const void* batch) {
    if (threadIdx.x == 0 && blockIdx.x == 0) {
        const int* p = (const int*)eidx;
        int a = 1;
        for (int i = 0; i < 64; i++) { if (p[2 * i + 1] != 0) { a = 0; break; } }
        g_flags[0] = a;
        const int* q = (const int*)batch;
        int b = 1;
        for (int i = 25001; i < 25128; i += 2) { if (q[i] != 0) { b = 0; break; } }
        g_flags[1] = b;
    }
}

// ---------------- copy x -> H ----------------
__global__ void copy_kernel(float4* __restrict__ dst, const float4* __restrict__ src, int n4) {
    for (int i = blockIdx.x * blockDim.x + threadIdx.x; i < n4; i += gridDim.x * blockDim.x)
        dst[i] = src[i];
}

// ---------------- fused node partials (unchanged, passing) ----------------
__global__ __launch_bounds__(368, 1) void prep_kernel(
    const float* __restrict__ H,
    const float* __restrict__ Wfl, const float* __restrict__ Wsl,
    const float* __restrict__ bfp, const float* __restrict__ bsp,
    float* __restrict__ Pd, float* __restrict__ Ps)
{
    extern __shared__ float sm[];
    float* Wsm = sm;             // [92][368]
    float* Asm = sm + AD * 368;  // [92][32] transposed
    const int t = threadIdx.x;
    {
        const float* src; int off;
        if (t < 92)       { src = Wfl;            off = t; }
        else if (t < 184) { src = Wsl;            off = t - 92; }
        else if (t < 276) { src = Wfl + 92 * AD;  off = t - 184; }
        else              { src = Wsl + 92 * AD;  off = t - 276; }
        for (int k = 0; k < AD; k++)
            Wsm[k * 368 + t] = src[k * AD + off];
    }
    const int cg = t % 92, eg = t / 92;
    const int j0 = 4 * cg;
    float4 bias = {0.f, 0.f, 0.f, 0.f};
    if (cg < 23)       bias = *(const float4*)(bfp + j0);
    else if (cg < 46)  bias = *(const float4*)(bsp + j0 - 92);
    float* outbase = (j0 < 184) ? Pd : Ps;
    const int ocol = (j0 < 184) ? j0 : (j0 - 184);
    const int ntiles = (NN + 31) / 32;
    for (int tile = blockIdx.x; tile < ntiles; tile += gridDim.x) {
        const int base = tile * 32;
        __syncthreads();
        if (t < 256) {
            const int r = t & 31, part = t >> 5;
            const int row = base + r;
            const float* src = H + (size_t)row * AD;
            for (int k = part; k < AD; k += 8)
                Asm[k * 32 + r] = (row < NN) ? src[k] : 0.f;
        }
        __syncthreads();
        u64 acc[8][2] = {};
        for (int k = 0; k < AD; k++) {
            const ulonglong2 w = *(const ulonglong2*)(Wsm + k * 368 + j0);
            const float4 a0 = *(const float4*)(Asm + k * 32 + 8 * eg);
            const float4 a1 = *(const float4*)(Asm + k * 32 + 8 * eg + 4);
            const float av[8] = {a0.x, a0.y, a0.z, a0.w, a1.x, a1.y, a1.z, a1.w};
            #pragma unroll
            for (int r = 0; r < 8; r++) {
                const u64 ap = pack2(av[r], av[r]);
                acc[r][0] = fma2(ap, w.x, acc[r][0]);
                acc[r][1] = fma2(ap, w.y, acc[r][1]);
            }
        }
        #pragma unroll
        for (int r = 0; r < 8; r++) {
            const int row = base + 8 * eg + r;
            if (row < NN) {
                float x0, x1, x2, x3;
                unpack2(acc[r][0], x0, x1); unpack2(acc[r][1], x2, x3);
                float4 o;
                o.x = x0 + bias.x; o.y = x1 + bias.y; o.z = x2 + bias.z; o.w = x3 + bias.w;
                *(float4*)(outbase + (size_t)row * PD + ocol) = o;
            }
        }
    }
}

// ---------------- mma.sync edge kernel ----------------
// Warp-tile: 16 edges x 192 cols (f 0..95 | s 96..191), K=48 (3 chunks of 16).
// 3-pass bf16 split (EhWh + EhWl + ElWh), fp32 accumulate in mma C-frags.
// A-frags built directly from gmem (no smem). B = W^T resident in smem, ldmatrix.
// Epilogue in-fragment: gather Pd/Ps, sigmoid*softplus, red.v2 into agg.
__global__ __launch_bounds__(128, 3) void edge_kernel_mma(
    const float* __restrict__ eattr, const void* __restrict__ eidx,
    const float* __restrict__ Wfe, const float* __restrict__ Wse,   // [41][92] slices
    const float* __restrict__ Pd, const float* __restrict__ Ps,
    float* __restrict__ agg)
{
    extern __shared__ char smc[];
    const uint32_t sb = smem_u32(smc);
    const int t = threadIdx.x;

    // ---- B fill: W^T rows n (0..191), cols k (0..47, pad to 64 bf16 = 128B rows)
    // row n: n<92 -> Wfe col n ; 96<=n<188 -> Wse col n-96 ; else zero
    for (int i = t; i < BROWS * 8; i += 128) {
        const int n = i >> 3, seg = i & 7;
        const float* wc = nullptr;
        if (n < 92)                  wc = Wfe + n;
        else if (n >= 96 && n < 188) wc = Wse + (n - 96);
        uint32_t hw[4], lw[4];
        #pragma unroll
        for (int p = 0; p < 4; p++) {
            const int k0 = seg * 8 + p * 2;
            const float x0 = (wc && k0     < ED) ? wc[(size_t)k0 * AD]       : 0.f;
            const float x1 = (wc && k0 + 1 < ED) ? wc[(size_t)(k0 + 1) * AD] : 0.f;
            __nv_bfloat16 h0, l0, h1, l1;
            bsplit(x0, h0, l0); bsplit(x1, h1, l1);
            hw[p] = pack_bf16x2(h0, h1);
            lw[p] = pack_bf16x2(l0, l1);
        }
        const int addr = n * BROWB + ((seg ^ (n & 7)) * 16);
        *(uint4*)(smc + OFF_BH + addr) = make_uint4(hw[0], hw[1], hw[2], hw[3]);
        *(uint4*)(smc + OFF_BL + addr) = make_uint4(lw[0], lw[1], lw[2], lw[3]);
    }
    __syncthreads();

    const int lane = t & 31;
    const int ll = g_flags[0];
    const int r0 = lane >> 2;            // 0..7
    const int kq = (lane & 3) * 2;       // 0,2,4,6
    // ldmatrix lane-address components (group g = lane>>3)
    const int ln_row = ((lane >> 4) & 1) * 8 + (lane & 7);  // row within 16-row frag pair
    const int ln_sgh = (lane >> 3) & 1;                     // seg parity (b0 vs b1)

    const int gw = blockIdx.x * 4 + (t >> 5);
    const int nw = gridDim.x * 4;
    const int ntiles = NE / 16;

    for (int tile = gw; tile < ntiles; tile += nw) {
        const int ebase = tile * 16;
        const int e0 = ebase + r0, e1 = e0 + 8;
        int d0, s0, d1, s1;
        if (ll) {
            const long long* ip = (const long long*)eidx;
            s0 = (int)ip[e0]; d0 = (int)ip[NE + e0];
            s1 = (int)ip[e1]; d1 = (int)ip[NE + e1];
        } else {
            const int* ip = (const int*)eidx;
            s0 = ip[e0]; d0 = ip[NE + e0];
            s1 = ip[e1]; d1 = ip[NE + e1];
        }

        float acc[24][4];
        #pragma unroll
        for (int j = 0; j < 24; j++) { acc[j][0] = acc[j][1] = acc[j][2] = acc[j][3] = 0.f; }

        const float* er0 = eattr + (size_t)e0 * ED;
        const float* er1 = eattr + (size_t)e1 * ED;

        for (int c = 0; c < 3; c++) {
            // ---- A frags from gmem, split hi/lo
            const int kA = 16 * c + kq;       // a0/a1 k-pos
            const int kB = kA + 8;            // a2/a3 k-pos
            uint32_t ah[4], al[4];
            {
                const float x00 = (kA     < ED) ? er0[kA]     : 0.f;
                const float x01 = (kA + 1 < ED) ? er0[kA + 1] : 0.f;
                const float x10 = (kA     < ED) ? er1[kA]     : 0.f;
                const float x11 = (kA + 1 < ED) ? er1[kA + 1] : 0.f;
                const float x02 = (kB     < ED) ? er0[kB]     : 0.f;
                const float x03 = (kB + 1 < ED) ? er0[kB + 1] : 0.f;
                const float x12 = (kB     < ED) ? er1[kB]     : 0.f;
                const float x13 = (kB + 1 < ED) ? er1[kB + 1] : 0.f;
                __nv_bfloat16 h0, l0, h1, l1;
                bsplit(x00, h0, l0); bsplit(x01, h1, l1);
                ah[0] = pack_bf16x2(h0, h1); al[0] = pack_bf16x2(l0, l1);
                bsplit(x10, h0, l0); bsplit(x11, h1, l1);
                ah[1] = pack_bf16x2(h0, h1); al[1] = pack_bf16x2(l0, l1);
                bsplit(x02, h0, l0); bsplit(x03, h1, l1);
                ah[2] = pack_bf16x2(h0, h1); al[2] = pack_bf16x2(l0, l1);
                bsplit(x12, h0, l0); bsplit(x13, h1, l1);
                ah[3] = pack_bf16x2(h0, h1); al[3] = pack_bf16x2(l0, l1);
            }
            // per-lane ldmatrix base offset for this chunk
            const uint32_t lb = (uint32_t)(ln_row * BROWB +
                                 (((2 * c + ln_sgh) ^ (lane & 7)) * 16));
            #pragma unroll
            for (int fp = 0; fp < 12; fp++) {
                uint32_t bh[4], bl[4];
                const uint32_t ao = lb + fp * (16 * BROWB);
                ldmatrix_x4(bh, sb + OFF_BH + ao);
                ldmatrix_x4(bl, sb + OFF_BL + ao);
                mma_bf16(acc[2 * fp],     ah, bh[0], bh[1]);   // hh
                mma_bf16(acc[2 * fp],     ah, bl[0], bl[1]);   // hl
                mma_bf16(acc[2 * fp],     al, bh[0], bh[1]);   // lh
                mma_bf16(acc[2 * fp + 1], ah, bh[2], bh[3]);
                mma_bf16(acc[2 * fp + 1], ah, bl[2], bl[3]);
                mma_bf16(acc[2 * fp + 1], al, bh[2], bh[3]);
            }
        }

        // ---- epilogue: frag j covers f-cols 8j + kq + {0,1}; s at frag j+12
        const float* pd0 = Pd + (size_t)d0 * PD;
        const float* ps0 = Ps + (size_t)s0 * PD;
        const float* pd1 = Pd + (size_t)d1 * PD;
        const float* ps1 = Ps + (size_t)s1 * PD;
        float* a0p = agg + (size_t)d0 * AD;
        float* a1p = agg + (size_t)d1 * AD;
        #pragma unroll
        for (int j = 0; j < 12; j++) {
            const int cf = 8 * j + kq;
            if (cf < 92) {
                // edge e0 (acc rows 0,1)
                {
                    const float2 gf_d = *(const float2*)(pd0 + cf);
                    const float2 gf_s = *(const float2*)(ps0 + cf);
                    const float2 gs_d = *(const float2*)(pd0 + 92 + cf);
                    const float2 gs_s = *(const float2*)(ps0 + 92 + cf);
                    const float f0 = acc[j][0] + gf_d.x + gf_s.x;
                    const float f1 = acc[j][1] + gf_d.y + gf_s.y;
                    const float v0 = acc[j + 12][0] + gs_d.x + gs_s.x;
                    const float v1 = acc[j + 12][1] + gs_d.y + gs_s.y;
                    red_add_v2(a0p + cf, sigmoidf_(f0) * softplusf_(v0),
                                          sigmoidf_(f1) * softplusf_(v1));
                }
                // edge e1 (acc rows 2,3)
                {
                    const float2 gf_d = *(const float2*)(pd1 + cf);
                    const float2 gf_s = *(const float2*)(ps1 + cf);
                    const float2 gs_d = *(const float2*)(pd1 + 92 + cf);
                    const float2 gs_s = *(const float2*)(ps1 + 92 + cf);
                    const float f0 = acc[j][2] + gf_d.x + gf_s.x;
                    const float f1 = acc[j][3] + gf_d.y + gf_s.y;
                    const float v0 = acc[j + 12][2] + gs_d.x + gs_s.x;
                    const float v1 = acc[j + 12][3] + gs_d.y + gs_s.y;
                    red_add_v2(a1p + cf, sigmoidf_(f0) * softplusf_(v0),
                                          sigmoidf_(f1) * softplusf_(v1));
                }
            }
        }
    }
}

// ---------------- batchnorm stats ----------------
__global__ void bn_stats(const float* __restrict__ agg, float* __restrict__ stats) {
    const int c = threadIdx.x;  // blockDim = 92
    float s = 0.f, q = 0.f;
    for (int i = blockIdx.x; i < NN; i += gridDim.x) {
        const float v = agg[(size_t)i * AD + c];
        s += v; q += v * v;
    }
    atomicAdd(&stats[c], s);
    atomicAdd(&stats[AD + c], q);
}

// ---------------- batchnorm apply + residual + leaky ----------------
__global__ void bn_apply(const float* __restrict__ agg, float* __restrict__ H,
                         const float* __restrict__ stats,
                         const float* __restrict__ gamma, const float* __restrict__ beta)
{
    const float invN = 1.f / (float)NN;
    for (int idx = blockIdx.x * blockDim.x + threadIdx.x; idx < NN * AD;
         idx += gridDim.x * blockDim.x) {
        const int c = idx % AD;
        const float mean = stats[c] * invN;
        const float var  = stats[AD + c] * invN - mean * mean;
        const float inv  = rsqrtf(var + 1e-5f);
        float v = (agg[idx] - mean) * inv * gamma[c] + beta[c] + H[idx];
        H[idx] = v > 0.f ? v : 0.01f * v;
    }
}

// ---------------- final MLP + pooling ----------------
__global__ __launch_bounds__(128) void mlp_pool(
    const float* __restrict__ H,
    const float* __restrict__ W1, const float* __restrict__ b1,
    const float* __restrict__ W2, const float* __restrict__ b2,
    const void* __restrict__ batch, float* __restrict__ pool)
{
    extern __shared__ float sm[];
    float* Wsm = sm;                 // [92][128]
    float* hsT = sm + AD * HID;      // [92][8]
    float* red = hsT + AD * 8;       // [4][8]
    const int t = threadIdx.x;
    for (int i = t; i < AD * HID; i += 128) Wsm[i] = W1[i];
    const float b1t = b1[t];
    const float w2t = W2[t];
    const int lane = t & 31, wid = t >> 5;
    const int ll = g_flags[1];
    const int ntiles = (NN + 7) / 8;
    for (int tile = blockIdx.x; tile < ntiles; tile += gridDim.x) {
        const int base = tile * 8;
        __syncthreads();
        for (int i = t; i < 8 * AD; i += 128) {
            int n = i / AD, k = i - n * AD;
            int node = base + n;
            hsT[k * 8 + n] = (node < NN) ? H[(size_t)node * AD + k] : 0.f;
        }
        __syncthreads();
        float acc[8] = {};
        #pragma unroll 4
        for (int k = 0; k < AD; k++) {
            const float w = Wsm[k * HID + t];
            const float4 h0 = *(const float4*)(hsT + k * 8);
            const float4 h1 = *(const float4*)(hsT + k * 8 + 4);
            acc[0] += h0.x * w; acc[1] += h0.y * w; acc[2] += h0.z * w; acc[3] += h0.w * w;
            acc[4] += h1.x * w; acc[5] += h1.y * w; acc[6] += h1.z * w; acc[7] += h1.w * w;
        }
        #pragma unroll
        for (int n = 0; n < 8; n++) {
            float v = acc[n] + b1t;
            v = v > 0.f ? v : 0.01f * v;
            v *= w2t;
            #pragma unroll
            for (int o = 16; o > 0; o >>= 1) v += __shfl_down_sync(0xffffffffu, v, o);
            if (lane == 0) red[wid * 8 + n] = v;
        }
        __syncthreads();
        if (t < 8) {
            const int node = base + t;
            if (node < NN) {
                const float s2 = red[t] + red[8 + t] + red[16 + t] + red[24 + t] + b2[0];
                const int g = ll ? (int)((const long long*)batch)[node]
                                 : ((const int*)batch)[node];
                atomicAdd(&pool[g], s2);
                atomicAdd(&pool[NG + g], 1.f);
            }
        }
    }
}

__global__ void finalize_kernel(const float* __restrict__ pool, float* __restrict__ out) {
    const int g = threadIdx.x;
    if (g < NG) out[g] = pool[g] / fmaxf(pool[NG + g], 1.f);
}

// ---------------- host orchestration ----------------
extern "C" void kernel_launch(void* const* d_in, const int* in_sizes, int n_in,
                              void* d_out, int out_size)
{
    const float* x     = (const float*)d_in[0];
    const void*  eidx  = d_in[1];
    const float* eattr = (const float*)d_in[2];
    const void*  batch = d_in[3];
    const float* Wf    = (const float*)d_in[4];
    const float* bf    = (const float*)d_in[5];
    const float* Ws    = (const float*)d_in[6];
    const float* bs    = (const float*)d_in[7];
    const float* gamma = (const float*)d_in[8];
    const float* beta  = (const float*)d_in[9];
    const float* W1    = (const float*)d_in[10];
    const float* b1    = (const float*)d_in[11];
    const float* W2    = (const float*)d_in[12];
    const float* b2    = (const float*)d_in[13];
    float* out = (float*)d_out;

    const int PREP_SMEM = (AD * 368 + AD * 32) * 4;       // 147200 B
    const int MLP_SMEM  = (AD * HID + AD * 8 + 32) * 4;   // 50304 B
    cudaFuncSetAttribute(prep_kernel,     cudaFuncAttributeMaxDynamicSharedMemorySize, PREP_SMEM);
    cudaFuncSetAttribute(mlp_pool,        cudaFuncAttributeMaxDynamicSharedMemorySize, MLP_SMEM);
    cudaFuncSetAttribute(edge_kernel_mma, cudaFuncAttributeMaxDynamicSharedMemorySize, EDGE_SMEM);

    void *pH, *pPd, *pPs, *pagg, *pstats, *ppool;
    cudaGetSymbolAddress(&pH, g_H);
    cudaGetSymbolAddress(&pPd, g_Pd);
    cudaGetSymbolAddress(&pPs, g_Ps);
    cudaGetSymbolAddress(&pagg, g_agg);
    cudaGetSymbolAddress(&pstats, g_stats);
    cudaGetSymbolAddress(&ppool, g_pool);

    detect_kernel<<<1, 32>>>(eidx, batch);
    copy_kernel<<<GRID, 256>>>((float4*)pH, (const float4*)x, NN * AD / 4);

    for (int l = 0; l < NL; l++) {
        const float* Wfl = Wf + (size_t)l * ZD * AD;
        const float* Wsl = Ws + (size_t)l * ZD * AD;
        prep_kernel<<<148, 368, PREP_SMEM>>>((const float*)pH, Wfl, Wsl,
                                             bf + l * AD, bs + l * AD,
                                             (float*)pPd, (float*)pPs);
        cudaMemsetAsync(pagg, 0, (size_t)NN * AD * sizeof(float));
        edge_kernel_mma<<<EGRID, 128, EDGE_SMEM>>>(eattr, eidx,
                                                   Wfl + 184 * AD, Wsl + 184 * AD,
                                                   (const float*)pPd, (const float*)pPs,
                                                   (float*)pagg);
        cudaMemsetAsync(pstats, 0, 2 * AD * sizeof(float));
        bn_stats<<<256, 92>>>((const float*)pagg, (float*)pstats);
        bn_apply<<<GRID, 256>>>((const float*)pagg, (float*)pH, (const float*)pstats,
                                gamma + l * AD, beta + l * AD);
    }

    cudaMemsetAsync(ppool, 0, 2 * NG * sizeof(float));
    mlp_pool<<<GRID, 128, MLP_SMEM>>>((const float*)pH, W1, b1, W2, b2, batch, (float*)ppool);
    finalize_kernel<<<1, NG>>>((const float*)ppool, out);
}